// round 1
// baseline (speedup 1.0000x reference)
#include <cuda_runtime.h>

#define NODES 8448
#define NB 10
#define ITERS 5
#define TPB 768
#define NPT 11          // 768 * 11 = 8448
#define NBATCH 1024

// smem: fp32 message buffer + u16 neighbor indices
#define SMEM_BYTES (NODES * 4 + NODES * NB * 2)   // 33792 + 168960 = 202752

__global__ __launch_bounds__(TPB, 1)
void ldpc_decoder_kernel(const float* __restrict__ input_llr,
                         const float* __restrict__ w_ch,
                         const float* __restrict__ w_res,     // (2, NODES)
                         const int*   __restrict__ check_idx, // (NODES, NB)
                         float*       __restrict__ out)
{
    extern __shared__ unsigned char smem_raw[];
    float*          vm   = reinterpret_cast<float*>(smem_raw);          // NODES floats
    unsigned short* sidx = reinterpret_cast<unsigned short*>(vm + NODES); // NODES*NB u16

    const int tid = threadIdx.x;
    const int b   = blockIdx.x;
    const float* llr = input_llr + (size_t)b * NODES;

    // Compress neighbor indices to u16 in SMEM (once per block).
    for (int k = tid; k < NODES * NB; k += TPB)
        sidx[k] = (unsigned short)check_idx[k];

    float wllr_r[NPT];    // weighted LLR (constant across iterations)
    float vmprev_r[NPT];  // var_messages from iteration t-1 (residual depth 2)
    float cur_r[NPT];     // scratch: old value in phase 1/2, new value after

    #pragma unroll
    for (int i = 0; i < NPT; i++) {
        const int n = tid + i * TPB;
        const float wl = llr[n] * w_ch[n];
        wllr_r[i]   = wl;
        vmprev_r[i] = 0.0f;
        vm[n]       = wl;      // var_messages = weighted_llr
    }
    __syncthreads();

    for (int it = 0; it < ITERS; it++) {
        // Phase 1: in-place replace vm[n] with t[n] = tanh(clip(0.5*vm[n]));
        // keep the old value in registers (each element touched by exactly one thread).
        #pragma unroll
        for (int i = 0; i < NPT; i++) {
            const int n = tid + i * TPB;
            const float v = vm[n];
            cur_r[i] = v;
            float x = fminf(9.9f, fmaxf(-9.9f, 0.5f * v));
            vm[n] = tanhf(x);
        }
        __syncthreads();

        // Phase 2: gather 10 precomputed tanh values, product, 2*atanh, residual.
        #pragma unroll
        for (int i = 0; i < NPT; i++) {
            const int n = tid + i * TPB;
            // 10 u16 indices = 20 bytes, 4B-aligned -> five u32 loads
            const unsigned int* ip = reinterpret_cast<const unsigned int*>(sidx + n * NB);
            float p = 1.0f;
            #pragma unroll
            for (int j = 0; j < NB / 2; j++) {
                const unsigned int pk = ip[j];
                p *= vm[pk & 0xFFFFu];
                p *= vm[pk >> 16];
            }
            p = fminf(0.999999f, fmaxf(-0.999999f, p));
            // 2 * atanh(p) = log((1+p)/(1-p))
            const float cm = logf((1.0f + p) / (1.0f - p));

            float res = w_res[n] * cur_r[i];                 // w_res[0][n] * vm_t
            if (it > 0) res += w_res[NODES + n] * vmprev_r[i]; // w_res[1][n] * vm_{t-1}

            const float newv = wllr_r[i] + cm + res;
            vmprev_r[i] = cur_r[i];
            cur_r[i]    = newv;
        }
        __syncthreads();

        // Phase 3: publish new var_messages.
        #pragma unroll
        for (int i = 0; i < NPT; i++)
            vm[tid + i * TPB] = cur_r[i];
        __syncthreads();
    }

    // soft_bits = sigmoid(var_messages + input_llr)
    #pragma unroll
    for (int i = 0; i < NPT; i++) {
        const int n = tid + i * TPB;
        const float z = cur_r[i] + llr[n];
        out[(size_t)b * NODES + n] = 1.0f / (1.0f + expf(-z));
    }
}

extern "C" void kernel_launch(void* const* d_in, const int* in_sizes, int n_in,
                              void* d_out, int out_size)
{
    const float* input_llr = (const float*)d_in[0];
    const float* w_ch      = (const float*)d_in[1];
    const float* w_res     = (const float*)d_in[2];
    const int*   check_idx = (const int*)d_in[3];
    // d_in[4] (var_index_tensor) is unused by the reference computation.
    float* out = (float*)d_out;

    cudaFuncSetAttribute(ldpc_decoder_kernel,
                         cudaFuncAttributeMaxDynamicSharedMemorySize, SMEM_BYTES);
    ldpc_decoder_kernel<<<NBATCH, TPB, SMEM_BYTES>>>(input_llr, w_ch, w_res,
                                                     check_idx, out);
}

// round 2
// speedup vs baseline: 1.1080x; 1.1080x over previous
#include <cuda_runtime.h>

#define NODES  8448
#define NB     10
#define ITERS  5
#define TPB    768
#define NPT    11            // 768 * 11 = 8448
#define NBATCH 1024
#define RPC    4             // batch rows per CTA (packed as float4)
#define NGROUPS (NBATCH / RPC)   // 256

#define SMEM_BYTES (NODES * 16)  // float4 tanh buffer = 135168 B

// Global scratch (static __device__ arrays; no allocation).
__device__ unsigned int g_pk[5][NODES];       // u16 neighbor ids, packed 2-per-u32, SoA
__device__ float4       g_wllr[NGROUPS][NODES];
__device__ float4       g_P[NGROUPS][NODES];  // vm_{t-1} (valid from iter 1 on)

// ---------------------------------------------------------------------------
// Prep: compress int32 indices (NODES x NB) -> u16 pairs, SoA over j.
__global__ void prep_idx_kernel(const int* __restrict__ check_idx)
{
    int k = blockIdx.x * blockDim.x + threadIdx.x;
    if (k < NODES * 5) {
        int n = k / 5, j = k % 5;
        unsigned a = (unsigned)check_idx[n * NB + 2 * j];
        unsigned b = (unsigned)check_idx[n * NB + 2 * j + 1];
        g_pk[j][n] = (a & 0xFFFFu) | (b << 16);
    }
}

// ---------------------------------------------------------------------------
__global__ __launch_bounds__(TPB, 1)
void ldpc4_kernel(const float* __restrict__ input_llr,
                  const float* __restrict__ w_ch,
                  const float* __restrict__ w_res,   // (2, NODES)
                  float*       __restrict__ out)
{
    extern __shared__ float4 st[];                   // tanh values, 4 rows packed
    const int tid  = threadIdx.x;
    const int g    = blockIdx.x;
    const int row0 = g * RPC;
    const float* llr0 = input_llr + (size_t)row0 * NODES;

    float4 cur[NPT];   // current var_messages for this thread's nodes (4 rows)

    // Prologue: weighted LLR -> registers + global scratch (reloaded each iter).
    #pragma unroll
    for (int i = 0; i < NPT; i++) {
        const int n = tid + i * TPB;
        const float wc = w_ch[n];
        float4 wl;
        wl.x = llr0[n]             * wc;
        wl.y = llr0[NODES + n]     * wc;
        wl.z = llr0[2 * NODES + n] * wc;
        wl.w = llr0[3 * NODES + n] * wc;
        g_wllr[g][n] = wl;
        cur[i] = wl;
    }

    for (int it = 0; it < ITERS; it++) {
        // Phase A: publish t = tanh(clip(0.5 * vm)) for all 4 rows (one LDS.128 store).
        #pragma unroll
        for (int i = 0; i < NPT; i++) {
            const int n = tid + i * TPB;
            const float4 v = cur[i];
            float4 t;
            t.x = tanhf(fminf(9.9f, fmaxf(-9.9f, 0.5f * v.x)));
            t.y = tanhf(fminf(9.9f, fmaxf(-9.9f, 0.5f * v.y)));
            t.z = tanhf(fminf(9.9f, fmaxf(-9.9f, 0.5f * v.z)));
            t.w = tanhf(fminf(9.9f, fmaxf(-9.9f, 0.5f * v.w)));
            st[n] = t;
        }
        __syncthreads();

        // Phase B: gather 10 neighbors (float4 LDS.128 serves 4 rows at once),
        // product -> 2*atanh, residual, update.
        #pragma unroll 2
        for (int i = 0; i < NPT; i++) {
            const int n = tid + i * TPB;
            float4 p = make_float4(1.f, 1.f, 1.f, 1.f);
            #pragma unroll
            for (int j = 0; j < 5; j++) {
                const unsigned pk = g_pk[j][n];
                const float4 a = st[pk & 0xFFFFu];
                const float4 b = st[pk >> 16];
                p.x *= a.x; p.y *= a.y; p.z *= a.z; p.w *= a.w;
                p.x *= b.x; p.y *= b.y; p.z *= b.z; p.w *= b.w;
            }
            p.x = fminf(0.999999f, fmaxf(-0.999999f, p.x));
            p.y = fminf(0.999999f, fmaxf(-0.999999f, p.y));
            p.z = fminf(0.999999f, fmaxf(-0.999999f, p.z));
            p.w = fminf(0.999999f, fmaxf(-0.999999f, p.w));
            float4 cm;
            cm.x = logf((1.0f + p.x) / (1.0f - p.x));   // 2*atanh(p)
            cm.y = logf((1.0f + p.y) / (1.0f - p.y));
            cm.z = logf((1.0f + p.z) / (1.0f - p.z));
            cm.w = logf((1.0f + p.w) / (1.0f - p.w));

            const float w0 = w_res[n];
            const float w1 = w_res[NODES + n];
            float4 pr = make_float4(0.f, 0.f, 0.f, 0.f);
            if (it > 0) pr = g_P[g][n];
            const float4 c = cur[i];
            g_P[g][n] = c;                              // becomes vm_{t-1} next iter
            const float4 wl = g_wllr[g][n];
            float4 nv;
            nv.x = wl.x + cm.x + w0 * c.x + w1 * pr.x;
            nv.y = wl.y + cm.y + w0 * c.y + w1 * pr.y;
            nv.z = wl.z + cm.z + w0 * c.z + w1 * pr.z;
            nv.w = wl.w + cm.w + w0 * c.w + w1 * pr.w;
            cur[i] = nv;
        }
        __syncthreads();   // protect st before next iteration's Phase A
    }

    // Epilogue: soft_bits = sigmoid(vm + input_llr), 4 coalesced row streams.
    #pragma unroll
    for (int i = 0; i < NPT; i++) {
        const int n = tid + i * TPB;
        const float4 c = cur[i];
        float* o = out + (size_t)row0 * NODES;
        const float zx = c.x + llr0[n];
        const float zy = c.y + llr0[NODES + n];
        const float zz = c.z + llr0[2 * NODES + n];
        const float zw = c.w + llr0[3 * NODES + n];
        o[n]             = 1.0f / (1.0f + expf(-zx));
        o[NODES + n]     = 1.0f / (1.0f + expf(-zy));
        o[2 * NODES + n] = 1.0f / (1.0f + expf(-zz));
        o[3 * NODES + n] = 1.0f / (1.0f + expf(-zw));
    }
}

// ---------------------------------------------------------------------------
extern "C" void kernel_launch(void* const* d_in, const int* in_sizes, int n_in,
                              void* d_out, int out_size)
{
    const float* input_llr = (const float*)d_in[0];
    const float* w_ch      = (const float*)d_in[1];
    const float* w_res     = (const float*)d_in[2];
    const int*   check_idx = (const int*)d_in[3];
    // d_in[4] (var_index_tensor) is unused by the reference computation.
    float* out = (float*)d_out;

    prep_idx_kernel<<<(NODES * 5 + 255) / 256, 256>>>(check_idx);

    cudaFuncSetAttribute(ldpc4_kernel,
                         cudaFuncAttributeMaxDynamicSharedMemorySize, SMEM_BYTES);
    ldpc4_kernel<<<NGROUPS, TPB, SMEM_BYTES>>>(input_llr, w_ch, w_res, out);
}